// round 3
// baseline (speedup 1.0000x reference)
#include <cuda_runtime.h>
#include <cstdint>

// Problem constants
#define S_LEN   64
#define D_MODEL 768
#define D_FFN   3072
#define RANK    16
#define MOD_SCALE 0.1f

// Packed f32x2 ops (ptxas won't auto-fuse these from C++).
#define FMA_F32X2(d, a, b, c) \
    asm("fma.rn.f32x2 %0, %1, %2, %3;" : "=l"(d) : "l"(a), "l"(b), "l"(c))
#define ADD_F32X2(d, a, b) \
    asm("add.rn.f32x2 %0, %1, %2;" : "=l"(d) : "l"(a), "l"(b))

// Scratch for modulation (64 x 16) — device global, no allocation.
__device__ float g_mod[S_LEN * RANK];

// ---------------------------------------------------------------------------
// Kernel 1: modulation[s][r] = 0.1 * tanh( sum_d attn[s][d] * A[d][r] )
// One block per s, 256 threads: thread = (chunk, r), 16 chunks x 48 d each,
// then a 16-way combine in smem.
// ---------------------------------------------------------------------------
__global__ __launch_bounds__(256)
void mod_kernel(const float* __restrict__ attn,
                const float* __restrict__ A)
{
    const int s     = blockIdx.x;
    const int r     = threadIdx.x & 15;
    const int chunk = threadIdx.x >> 4;          // 0..15
    const int d0    = chunk * (D_MODEL / 16);    // 48 d per chunk

    const float* arow = attn + (size_t)s * D_MODEL;
    float acc = 0.0f;
#pragma unroll 4
    for (int d = d0; d < d0 + (D_MODEL / 16); d++) {
        acc += arow[d] * A[d * RANK + r];
    }

    __shared__ float part[16][RANK];
    part[chunk][r] = acc;
    __syncthreads();

    if (threadIdx.x < RANK) {
        float t = 0.0f;
#pragma unroll
        for (int c = 0; c < 16; c++) t += part[c][threadIdx.x];
        g_mod[s * RANK + threadIdx.x] = MOD_SCALE * tanhf(t);
    }
}

// ---------------------------------------------------------------------------
// Kernel 2: delta_w[p][f] = sum_r C[p][r] * B[r][f],  p = s*768 + d,
//           C[p][r] = mod[s][r] * A[d][r]
//
// Occupancy-focused shape: each thread owns 2 consecutive f (one packed
// f32x2 accumulator). B slab = 16 packed regs (32 regs) -> ~55-60 regs
// total -> 4 blocks/SM (50% occ) to hide store backpressure.
// Per pair per thread: 8x LDS.128 broadcast (pre-dup'd {c,c}) + 16 FFMA2
// on two independent chains + 1 streaming STG.64.
// ---------------------------------------------------------------------------
#define FTILE       512
#define PAIRS_PER_B 128
#define THREADS     256

__global__ __launch_bounds__(THREADS, 4)
void deltaw_kernel(const float* __restrict__ A,
                   const float* __restrict__ B,
                   float* __restrict__ out)
{
    const int f0    = blockIdx.y * FTILE + threadIdx.x * 2;
    const int pair0 = blockIdx.x * PAIRS_PER_B;

    // B slab in registers: Breg[r] = packed {B[r][f0], B[r][f0+1]}
    uint64_t Breg[RANK];
#pragma unroll
    for (int r = 0; r < RANK; r++) {
        Breg[r] = *reinterpret_cast<const uint64_t*>(&B[r * D_FFN + f0]);
    }

    // C duplicated for packed math: Cs[p][r] = {c, c}.
    __shared__ float2 Cs[PAIRS_PER_B][RANK];
    for (int i = threadIdx.x; i < PAIRS_PER_B * RANK; i += THREADS) {
        const int p  = i >> 4;
        const int r  = i & 15;
        const int pd = pair0 + p;
        const int s  = pd / D_MODEL;
        const int d  = pd % D_MODEL;
        const float c = g_mod[s * RANK + r] * A[d * RANK + r];
        Cs[p][r] = make_float2(c, c);
    }
    __syncthreads();

    float* outp = out + (size_t)pair0 * D_FFN + f0;
#pragma unroll 2
    for (int p = 0; p < PAIRS_PER_B; p++) {
        const ulonglong2* cp = reinterpret_cast<const ulonglong2*>(&Cs[p][0]);
        uint64_t accA = 0ull;   // two independent chains, combined at the end
        uint64_t accB = 0ull;
#pragma unroll
        for (int i = 0; i < 8; i++) {
            const ulonglong2 cc = cp[i];   // one LDS.128 -> {c2i,c2i},{c2i+1,c2i+1}
            FMA_F32X2(accA, cc.x, Breg[2 * i],     accA);
            FMA_F32X2(accB, cc.y, Breg[2 * i + 1], accB);
        }
        uint64_t acc;
        ADD_F32X2(acc, accA, accB);
        float2 v;
        v.x = __uint_as_float((uint32_t)(acc & 0xFFFFFFFFull));
        v.y = __uint_as_float((uint32_t)(acc >> 32));
        __stcs(reinterpret_cast<float2*>(outp), v);   // streaming store
        outp += D_FFN;
    }
}

// ---------------------------------------------------------------------------
// Launch
// ---------------------------------------------------------------------------
extern "C" void kernel_launch(void* const* d_in, const int* in_sizes, int n_in,
                              void* d_out, int out_size)
{
    const float* attn = (const float*)d_in[0];  // (1, 64, 768)
    const float* A    = (const float*)d_in[1];  // (768, 16)
    const float* B    = (const float*)d_in[2];  // (16, 3072)
    float* out        = (float*)d_out;          // (1, 64, 768, 3072)

    mod_kernel<<<S_LEN, 256>>>(attn, A);

    dim3 grid((S_LEN * D_MODEL) / PAIRS_PER_B,  // 384
              D_FFN / FTILE);                   // 6
    deltaw_kernel<<<grid, THREADS>>>(A, B, out);
}

// round 4
// speedup vs baseline: 1.6007x; 1.6007x over previous
#include <cuda_runtime.h>
#include <cstdint>

// Problem constants
#define S_LEN   64
#define D_MODEL 768
#define D_FFN   3072
#define RANK    16
#define MOD_SCALE 0.1f

// Packed f32x2 FMA (ptxas won't auto-fuse from C++).
#define FMA_F32X2(d, a, b, c) \
    asm("fma.rn.f32x2 %0, %1, %2, %3;" : "=l"(d) : "l"(a), "l"(b), "l"(c))
// Duplicate a scalar float into a packed {s,s} 64-bit operand (1 MOV in SASS).
#define DUP_F32X2(d, s) \
    asm("mov.b64 %0, {%1, %1};" : "=l"(d) : "r"(__float_as_uint(s)))

// Scratch for modulation (64 x 16) — device global, no allocation.
__device__ float g_mod[S_LEN * RANK];

// ---------------------------------------------------------------------------
// Kernel 1: modulation[s][r] = 0.1 * tanh( sum_d attn[s][d] * A[d][r] )
// One block per s, 256 threads: thread = (chunk, r), 16 chunks x 48 d each,
// then a 16-way combine in smem.
// ---------------------------------------------------------------------------
__global__ __launch_bounds__(256)
void mod_kernel(const float* __restrict__ attn,
                const float* __restrict__ A)
{
    const int s     = blockIdx.x;
    const int r     = threadIdx.x & 15;
    const int chunk = threadIdx.x >> 4;          // 0..15
    const int d0    = chunk * (D_MODEL / 16);    // 48 d per chunk

    const float* arow = attn + (size_t)s * D_MODEL;
    float acc = 0.0f;
#pragma unroll 4
    for (int d = d0; d < d0 + (D_MODEL / 16); d++) {
        acc += arow[d] * A[d * RANK + r];
    }

    __shared__ float part[16][RANK];
    part[chunk][r] = acc;
    __syncthreads();

    if (threadIdx.x < RANK) {
        float t = 0.0f;
#pragma unroll
        for (int c = 0; c < 16; c++) t += part[c][threadIdx.x];
        g_mod[s * RANK + threadIdx.x] = MOD_SCALE * tanhf(t);
    }
}

// ---------------------------------------------------------------------------
// Kernel 2: delta_w[p][f] = sum_r C[p][r] * B[r][f],  p = s*768 + d,
//           C[p][r] = mod[s][r] * A[d][r]
//
// R2 geometry (4 f per thread, FTILE=1024, B slab register-resident), but C
// is stored NON-duplicated in smem (64 B/pair -> 4 broadcast LDS.128/pair)
// and the packed {c,c} operands are built in-register with mov.b64 (ALU
// pipe, parallel to the FMA pipe). Per pair per thread:
//   4x LDS.128 + 16x MOV-dup + 32x FFMA2 + 1x streaming STG.128.
// ---------------------------------------------------------------------------
#define FTILE       1024
#define PAIRS_PER_B 128
#define THREADS     256

__global__ __launch_bounds__(THREADS)
void deltaw_kernel(const float* __restrict__ A,
                   const float* __restrict__ B,
                   float* __restrict__ out)
{
    const int f0    = blockIdx.y * FTILE + threadIdx.x * 4;
    const int pair0 = blockIdx.x * PAIRS_PER_B;

    // B slab in registers as packed f32x2 halves:
    // Breg[r] = { {B[r][f0],B[r][f0+1]}, {B[r][f0+2],B[r][f0+3]} }
    ulonglong2 Breg[RANK];
#pragma unroll
    for (int r = 0; r < RANK; r++) {
        Breg[r] = *reinterpret_cast<const ulonglong2*>(&B[r * D_FFN + f0]);
    }

    // C non-duplicated: Cs[p][r] = mod[s][r] * A[d][r]  (16 floats per pair).
    __shared__ float Cs[PAIRS_PER_B][RANK];
    for (int i = threadIdx.x; i < PAIRS_PER_B * RANK; i += THREADS) {
        const int p  = i >> 4;
        const int r  = i & 15;
        const int pd = pair0 + p;
        const int s  = pd / D_MODEL;
        const int d  = pd % D_MODEL;
        Cs[p][r] = g_mod[s * RANK + r] * A[d * RANK + r];
    }
    __syncthreads();

    float* outp = out + (size_t)pair0 * D_FFN + f0;
#pragma unroll 2
    for (int p = 0; p < PAIRS_PER_B; p++) {
        const float4* cp = reinterpret_cast<const float4*>(&Cs[p][0]);
        uint64_t a0 = 0ull;   // packed accum for {f0, f0+1}
        uint64_t a1 = 0ull;   // packed accum for {f0+2, f0+3}
#pragma unroll
        for (int i = 0; i < 4; i++) {
            const float4 c4 = cp[i];          // one broadcast LDS.128: 4 r-values
            uint64_t d0, d1, d2, d3;
            DUP_F32X2(d0, c4.x);
            DUP_F32X2(d1, c4.y);
            DUP_F32X2(d2, c4.z);
            DUP_F32X2(d3, c4.w);
            FMA_F32X2(a0, d0, Breg[4 * i + 0].x, a0);
            FMA_F32X2(a1, d0, Breg[4 * i + 0].y, a1);
            FMA_F32X2(a0, d1, Breg[4 * i + 1].x, a0);
            FMA_F32X2(a1, d1, Breg[4 * i + 1].y, a1);
            FMA_F32X2(a0, d2, Breg[4 * i + 2].x, a0);
            FMA_F32X2(a1, d2, Breg[4 * i + 2].y, a1);
            FMA_F32X2(a0, d3, Breg[4 * i + 3].x, a0);
            FMA_F32X2(a1, d3, Breg[4 * i + 3].y, a1);
        }
        float4 v;
        v.x = __uint_as_float((uint32_t)(a0 & 0xFFFFFFFFull));
        v.y = __uint_as_float((uint32_t)(a0 >> 32));
        v.z = __uint_as_float((uint32_t)(a1 & 0xFFFFFFFFull));
        v.w = __uint_as_float((uint32_t)(a1 >> 32));
        __stcs(reinterpret_cast<float4*>(outp), v);   // streaming store
        outp += D_FFN;
    }
}

// ---------------------------------------------------------------------------
// Launch
// ---------------------------------------------------------------------------
extern "C" void kernel_launch(void* const* d_in, const int* in_sizes, int n_in,
                              void* d_out, int out_size)
{
    const float* attn = (const float*)d_in[0];  // (1, 64, 768)
    const float* A    = (const float*)d_in[1];  // (768, 16)
    const float* B    = (const float*)d_in[2];  // (16, 3072)
    float* out        = (float*)d_out;          // (1, 64, 768, 3072)

    mod_kernel<<<S_LEN, 256>>>(attn, A);

    dim3 grid((S_LEN * D_MODEL) / PAIRS_PER_B,  // 384
              D_FFN / FTILE);                   // 3
    deltaw_kernel<<<grid, THREADS>>>(A, B, out);
}

// round 5
// speedup vs baseline: 1.6401x; 1.0246x over previous
#include <cuda_runtime.h>
#include <cstdint>

// Problem constants
#define S_LEN   64
#define D_MODEL 768
#define D_FFN   3072
#define RANK    16
#define MOD_SCALE 0.1f

// Packed f32x2 FMA (ptxas won't auto-fuse from C++).
#define FMA_F32X2(d, a, b, c) \
    asm("fma.rn.f32x2 %0, %1, %2, %3;" : "=l"(d) : "l"(a), "l"(b), "l"(c))
// Duplicate a scalar float into a packed {s,s} 64-bit operand.
#define DUP_F32X2(d, s) \
    asm("mov.b64 %0, {%1, %1};" : "=l"(d) : "r"(__float_as_uint(s)))

// Scratch for modulation (64 x 16) — device global, no allocation.
__device__ float g_mod[S_LEN * RANK];

// ---------------------------------------------------------------------------
// Kernel 1: modulation[s][r] = 0.1 * tanh( sum_d attn[s][d] * A[d][r] )
// ---------------------------------------------------------------------------
__global__ __launch_bounds__(256)
void mod_kernel(const float* __restrict__ attn,
                const float* __restrict__ A)
{
    const int s     = blockIdx.x;
    const int r     = threadIdx.x & 15;
    const int chunk = threadIdx.x >> 4;          // 0..15
    const int d0    = chunk * (D_MODEL / 16);    // 48 d per chunk

    const float* arow = attn + (size_t)s * D_MODEL;
    float acc = 0.0f;
#pragma unroll 4
    for (int d = d0; d < d0 + (D_MODEL / 16); d++) {
        acc += arow[d] * A[d * RANK + r];
    }

    __shared__ float part[16][RANK];
    part[chunk][r] = acc;
    __syncthreads();

    if (threadIdx.x < RANK) {
        float t = 0.0f;
#pragma unroll
        for (int c = 0; c < 16; c++) t += part[c][threadIdx.x];
        g_mod[s * RANK + threadIdx.x] = MOD_SCALE * tanhf(t);
    }
}

// ---------------------------------------------------------------------------
// Kernel 2: delta_w[p][f] = sum_r C[p][r] * B[r][f],  p = s*768 + d,
//           C[p][r] = mod[s][r] * A[d][r]
//
// R4 math (non-dup C in smem, mov.b64 dup, packed FFMA2, streaming STG.128)
// with residency/scheduling fixes:
//  - __launch_bounds__(256, 3): cap regs ~85 -> 3 CTAs/SM (24 warps, 37% occ)
//  - PAIRS_PER_B 64: ~7us blocks -> small drain tail, work-steal friendly
// Per pair per thread: 4x LDS.128 broadcast + 16 dup + 32 FFMA2 + 1 STG.128.
// ---------------------------------------------------------------------------
#define FTILE       1024
#define PAIRS_PER_B 64
#define THREADS     256

__global__ __launch_bounds__(THREADS, 3)
void deltaw_kernel(const float* __restrict__ A,
                   const float* __restrict__ B,
                   float* __restrict__ out)
{
    const int f0    = blockIdx.y * FTILE + threadIdx.x * 4;
    const int pair0 = blockIdx.x * PAIRS_PER_B;

    // B slab in registers as packed f32x2 halves.
    ulonglong2 Breg[RANK];
#pragma unroll
    for (int r = 0; r < RANK; r++) {
        Breg[r] = *reinterpret_cast<const ulonglong2*>(&B[r * D_FFN + f0]);
    }

    // C non-duplicated: Cs[p][r] = mod[s][r] * A[d][r].
    __shared__ float Cs[PAIRS_PER_B][RANK];
    for (int i = threadIdx.x; i < PAIRS_PER_B * RANK; i += THREADS) {
        const int p  = i >> 4;
        const int r  = i & 15;
        const int pd = pair0 + p;
        const int s  = pd / D_MODEL;
        const int d  = pd % D_MODEL;
        Cs[p][r] = g_mod[s * RANK + r] * A[d * RANK + r];
    }
    __syncthreads();

    float* outp = out + (size_t)pair0 * D_FFN + f0;
#pragma unroll 1
    for (int p = 0; p < PAIRS_PER_B; p++) {
        const float4* cp = reinterpret_cast<const float4*>(&Cs[p][0]);
        uint64_t a0 = 0ull;   // packed accum for {f0, f0+1}
        uint64_t a1 = 0ull;   // packed accum for {f0+2, f0+3}
#pragma unroll
        for (int i = 0; i < 4; i++) {
            const float4 c4 = cp[i];          // one broadcast LDS.128: 4 r-values
            uint64_t d0, d1, d2, d3;
            DUP_F32X2(d0, c4.x);
            DUP_F32X2(d1, c4.y);
            DUP_F32X2(d2, c4.z);
            DUP_F32X2(d3, c4.w);
            FMA_F32X2(a0, d0, Breg[4 * i + 0].x, a0);
            FMA_F32X2(a1, d0, Breg[4 * i + 0].y, a1);
            FMA_F32X2(a0, d1, Breg[4 * i + 1].x, a0);
            FMA_F32X2(a1, d1, Breg[4 * i + 1].y, a1);
            FMA_F32X2(a0, d2, Breg[4 * i + 2].x, a0);
            FMA_F32X2(a1, d2, Breg[4 * i + 2].y, a1);
            FMA_F32X2(a0, d3, Breg[4 * i + 3].x, a0);
            FMA_F32X2(a1, d3, Breg[4 * i + 3].y, a1);
        }
        float4 v;
        v.x = __uint_as_float((uint32_t)(a0 & 0xFFFFFFFFull));
        v.y = __uint_as_float((uint32_t)(a0 >> 32));
        v.z = __uint_as_float((uint32_t)(a1 & 0xFFFFFFFFull));
        v.w = __uint_as_float((uint32_t)(a1 >> 32));
        __stcs(reinterpret_cast<float4*>(outp), v);   // streaming store
        outp += D_FFN;
    }
}

// ---------------------------------------------------------------------------
// Launch
// ---------------------------------------------------------------------------
extern "C" void kernel_launch(void* const* d_in, const int* in_sizes, int n_in,
                              void* d_out, int out_size)
{
    const float* attn = (const float*)d_in[0];  // (1, 64, 768)
    const float* A    = (const float*)d_in[1];  // (768, 16)
    const float* B    = (const float*)d_in[2];  // (16, 3072)
    float* out        = (float*)d_out;          // (1, 64, 768, 3072)

    mod_kernel<<<S_LEN, 256>>>(attn, A);

    dim3 grid((S_LEN * D_MODEL) / PAIRS_PER_B,  // 768
              D_FFN / FTILE);                   // 3
    deltaw_kernel<<<grid, THREADS>>>(A, B, out);
}